// round 15
// baseline (speedup 1.0000x reference)
#include <cuda_runtime.h>
#include <cuda_bf16.h>
#include <cuda_fp16.h>
#include <math.h>
#include <stdint.h>
#include <string.h>

// ---------------- problem constants ----------------
#define BN      16384
#define HIDN    512
#define G4      2048
#define HLEN    15
#define DIM     1024

// ---------------- LSTM mma bf16 config ----------------
#define LTPB    512            // 16 warps (4 per SMSP)
#define NCTA1   148            // wave-1 CTAs: 64 rows
#define NCTA2   144            // wave-2 CTAs: 48 rows   (148*64+144*48 = 16384)
#define KSLN    33             // K slices: 512 h + 16 (x,1,pad)
#define HRW     268            // h row stride in u32 words (=536 bf16); conflict-free

// smem layout (bytes) — sized for 64 rows
#define OFF_H0   0              // 64*536*2 = 68608
#define OFF_H1   68608
#define OFF_C    137216         // c fp16 [64 slots][512 tid]; reused as LN scratch in tail
#define OFF_TRJ  202752         // 64*60*4 = 15360
#define OFF_ALF  218112         // 32 f32 alphas
#define LSMEM    218240

// ---------------- device scratch ----------------
// W_hh(+W_ih+bias): per (pass,ksl,w16) tile of 256 u32: lane*8 + nt*2 + jj
__device__ uint32_t g_Wf [4*KSLN*16*256];
// W_rel: per (ch,w16,ksl) tile of 256 u32: lane*8 + nt*2 + jj
__device__ uint32_t g_Wrf[2*16*32*256];

// ---------------- helpers ----------------
__device__ __forceinline__ float tanh_ap(float x){
    float y; asm("tanh.approx.f32 %0, %1;" : "=f"(y) : "f"(x)); return y;
}
__device__ __forceinline__ float sig_ap(float x){
    return fmaf(tanh_ap(0.5f*x), 0.5f, 0.5f);
}
__device__ __forceinline__ uint32_t smem_u32(const void* p){
    uint32_t a; asm("{ .reg .u64 t; cvta.to.shared.u64 t, %1; cvt.u32.u64 %0, t; }":"=r"(a):"l"(p)); return a;
}
#define MMA_BF16(c, a, b0, b1) \
    asm volatile("mma.sync.aligned.m16n8k16.row.col.f32.bf16.bf16.f32 " \
        "{%0,%1,%2,%3}, {%4,%5,%6,%7}, {%8,%9}, {%0,%1,%2,%3};" \
        : "+f"((c)[0]), "+f"((c)[1]), "+f"((c)[2]), "+f"((c)[3]) \
        : "r"((a)[0]), "r"((a)[1]), "r"((a)[2]), "r"((a)[3]), "r"(b0), "r"(b1))
#define LDSM4(r, addr) \
    asm volatile("ldmatrix.sync.aligned.m8n8.x4.shared.b16 {%0,%1,%2,%3}, [%4];" \
        : "=r"((r)[0]), "=r"((r)[1]), "=r"((r)[2]), "=r"((r)[3]) : "r"(addr))

__device__ __forceinline__ uint32_t bf2(float a, float b){
    __nv_bfloat162 p = __floats2bfloat162_rn(a, b);
    uint32_t u; memcpy(&u, &p, 4); return u;
}

// ---------------------------------------------------------------------------
// reorder: W_hh (+W_ih+bias slice 32) -> g_Wf; W_rel -> g_Wrf. LDG.128 layout.
// ---------------------------------------------------------------------------
__global__ void reorder_kernel(const float* __restrict__ Whh, const float* __restrict__ Wih,
                               const float* __restrict__ bih, const float* __restrict__ bhh,
                               const float* __restrict__ Wrel)
{
    if (blockIdx.x < G4) {
        int n = blockIdx.x;
        int pass = n >> 9, w16 = (n >> 5) & 15, cw = n & 31;
        int j = cw >> 3, qq = (cw >> 1) & 3, r = cw & 1;
        int gate, ul;
        if (j < 2) { ul = j*4 + qq;     gate = r;     }
        else       { ul = (j-2)*4 + qq; gate = 2 + r; }
        int unit = pass*128 + w16*8 + ul;
        int srow = gate * HIDN + unit;

        const float* src = Whh + (size_t)srow * HIDN;
        float bsum = bih[srow] + bhh[srow];
        int colin = cw & 7;

        for (int k2 = threadIdx.x; k2 < (KSLN*16)/2; k2 += blockDim.x) {
            int k = k2 * 2;
            int ksl = k >> 4, kin = k & 15;
            float v0, v1;
            if (ksl < 32) { v0 = src[k]; v1 = src[k+1]; }
            else {
                v0 = (kin < 4) ? Wih[srow*4 + kin] : (kin == 4 ? bsum : 0.0f);
                v1 = (kin + 1 < 4) ? Wih[srow*4 + kin + 1] : 0.0f;
            }
            int jj = kin >> 3, qk = (kin >> 1) & 3;
            int lane = colin*4 + qk;
            size_t idx = ((size_t)((pass*KSLN + ksl)*16 + w16))*256 + lane*8 + j*2 + jj;
            g_Wf[idx] = bf2(v0, v1);
        }
    } else {
        int n = blockIdx.x - G4;            // output col 0..1023
        const float* src = Wrel + (size_t)n * HIDN;
        int ch = n >> 9, w16 = (n >> 5) & 15, nt = (n >> 3) & 3, colin = n & 7;
        for (int k2 = threadIdx.x; k2 < HIDN/2; k2 += blockDim.x) {
            int k = k2 * 2;
            int ksl = k >> 4, kin = k & 15;
            int jj = kin >> 3, qk = (kin >> 1) & 3;
            int lane = colin*4 + qk;
            size_t idx = ((size_t)((ch*16 + w16)*32 + ksl))*256 + lane*8 + nt*2 + jj;
            g_Wrf[idx] = bf2(src[k], src[k+1]);
        }
    }
}

// ---------------------------------------------------------------------------
// LSTM + fused projection/LN body, templated on m-tiles (4 -> 64 rows, 3 -> 48).
// ---------------------------------------------------------------------------
template<int MTN>
__device__ __forceinline__ void lstm_fuse_body(
    const float* __restrict__ traj, const float* __restrict__ tokens,
    const float* __restrict__ habs,
    const float* __restrict__ espeed, const float* __restrict__ gconf,
    const float* __restrict__ Wg1, const float* __restrict__ bg1,
    const float* __restrict__ Wg2, const float* __restrict__ bg2,
    const float* __restrict__ W_abs,
    const float* __restrict__ gamma, const float* __restrict__ beta,
    float* __restrict__ out, int m0)
{
    extern __shared__ char smem[];
    float*  trj = (float*) (smem + OFF_TRJ);
    __half* c_s = (__half*)(smem + OFF_C);
    float*  alf = (float*) (smem + OFF_ALF);
    const int ROWS = MTN * 16;

    const int tid = threadIdx.x;
    const int lane = tid & 31, warpid = tid >> 5;
    const int q = lane & 3, g8 = lane >> 2;

    // per-CTA alpha gate for all 32 batches (tiny MLP)
    if (tid < 32) {
        float s = espeed[tid], cg = gconf[tid];
        float acc = bg2[0];
        #pragma unroll
        for (int h = 0; h < 16; ++h) {
            float tv = Wg1[2*h]*s + Wg1[2*h+1]*cg + bg1[h];
            acc += Wg2[h] * fmaxf(tv, 0.0f);
        }
        alf[tid] = 1.0f / (1.0f + expf(-acc));
    }

    for (int i = tid; i < (ROWS*HLEN*4)/4; i += LTPB)
        ((float4*)trj)[i] = ((const float4*)(traj + (size_t)m0 * (HLEN*4)))[i];
    if (tid < ROWS) {
        float4 xv = *(const float4*)(traj + (size_t)(m0 + tid) * (HLEN*4));
        uint32_t* dst = (uint32_t*)(smem + OFF_H0) + tid*HRW + 256;
        dst[0] = bf2(xv.x, xv.y); dst[1] = bf2(xv.z, xv.w); dst[2] = bf2(1.0f, 0.0f);
        dst[3] = 0; dst[4] = 0; dst[5] = 0; dst[6] = 0; dst[7] = 0;
    }
    __syncthreads();

    const uint4* __restrict__ Wf128 = (const uint4*)g_Wf;
    const uint32_t lmoff = (((lane & 15) * HRW + ((lane >> 4) << 2)) << 2);
    const uint32_t h0b = smem_u32(smem + OFF_H0) + lmoff;
    const uint32_t h1b = smem_u32(smem + OFF_H1) + lmoff;
    const uint32_t lq = (uint32_t)lane * 2;      // uint4 offset within tile

    // persistent B stage: preload (t=0, ncp=0, ksl=KSLN-1)
    uint4 c0, c1;
    {
        const uint4* B0 = Wf128 + ((size_t)((0*KSLN + (KSLN-1))*16 + warpid))*64 + lq;
        c0 = B0[0]; c1 = B0[1];
    }

    for (int t = 0; t < HLEN; ++t) {
        const uint32_t hcur_b = (t & 1) ? h1b : h0b;
        char*          hnb  = smem + ((t & 1) ? OFF_H0 : OFF_H1);
        __nv_bfloat16* hnxt = (__nv_bfloat16*)hnb;

        for (int ncp = 0; ncp < 4; ++ncp) {
            float acc[MTN][4][4];
            #pragma unroll
            for (int mt = 0; mt < MTN; ++mt)
                #pragma unroll
                for (int nt = 0; nt < 4; ++nt)
                    #pragma unroll
                    for (int c = 0; c < 4; ++c) acc[mt][nt][c] = 0.0f;

            const int ks0 = (t == 0) ? (KSLN - 1) : 0;
            const uint4* Bp = Wf128 + ((size_t)(ncp*KSLN*16) + warpid)*64 + lq;

            for (int ksl = ks0; ksl < KSLN; ++ksl) {
                uint4 n0, n1;
                if (ksl < KSLN - 1) {
                    const uint4* Bn = Bp + (size_t)(ksl + 1) * 1024;
                    n0 = Bn[0]; n1 = Bn[1];
                }
                uint32_t a[MTN][4];
                const uint32_t aaddr = hcur_b + ksl*32;
                #pragma unroll
                for (int mt = 0; mt < MTN; ++mt)
                    LDSM4(a[mt], aaddr + mt*(16*HRW*4));
                #pragma unroll
                for (int mt = 0; mt < MTN; ++mt) {
                    MMA_BF16(acc[mt][0], a[mt], c0.x, c0.y);
                    MMA_BF16(acc[mt][1], a[mt], c0.z, c0.w);
                    MMA_BF16(acc[mt][2], a[mt], c1.x, c1.y);
                    MMA_BF16(acc[mt][3], a[mt], c1.z, c1.w);
                }
                c0 = n0; c1 = n1;
            }

            // prefetch next (pass, step)'s first B tile — overlaps epilogue
            {
                int tn = t, ncpn = ncp + 1;
                if (ncpn == 4) { ncpn = 0; tn = t + 1; }
                if (tn < HLEN) {
                    int ks0n = (tn == 0) ? (KSLN - 1) : 0;
                    const uint4* Bq = Wf128 + ((size_t)((ncpn*KSLN + ks0n)*16) + warpid)*64 + lq;
                    c0 = Bq[0]; c1 = Bq[1];
                }
            }

            // ---- epilogue ----
            #pragma unroll
            for (int j2 = 0; j2 < 2; ++j2) {
                const int kg = ncp*128 + warpid*8 + j2*4 + q;
                #pragma unroll
                for (int mt = 0; mt < MTN; ++mt) {
                    #pragma unroll
                    for (int half = 0; half < 2; ++half) {
                        const int row = mt*16 + g8 + half*8;
                        const float gi = acc[mt][j2  ][half*2  ];
                        const float gf = acc[mt][j2  ][half*2+1];
                        const float gg = acc[mt][j2+2][half*2  ];
                        const float go = acc[mt][j2+2][half*2+1];
                        const int cidx = ((ncp*2 + j2)*8 + mt*2 + half)*LTPB + tid;
                        float cp = (t > 0) ? __half2float(c_s[cidx]) : 0.0f;
                        float cn = sig_ap(gf) * cp + sig_ap(gi) * tanh_ap(gg);
                        c_s[cidx] = __float2half(cn);
                        float hn = sig_ap(go) * tanh_ap(cn);
                        hnxt[row*536 + kg] = __float2bfloat16_rn(hn);
                    }
                }
            }
        }

        if (t < HLEN - 1 && tid < ROWS) {
            float4 xv = *(const float4*)(trj + tid*60 + (t+1)*4);
            uint32_t* dst = (uint32_t*)hnb + tid*HRW + 256;
            dst[0] = bf2(xv.x, xv.y); dst[1] = bf2(xv.z, xv.w); dst[2] = bf2(1.0f, 0.0f);
            dst[3] = 0; dst[4] = 0; dst[5] = 0; dst[6] = 0; dst[7] = 0;
        }
        __syncthreads();
    }

    // =======================================================================
    // fuse tail: out = LN(tokens + al*(h15 @ W_rel^T) + (1-al)*(habs @ W_abs^T))
    // =======================================================================
    float* redS = (float*)(smem + OFF_C);      // [64][64]
    float* redQ = redS + 64*64;
    float* mu_s = redQ + 64*64;
    float* rs_s = mu_s + 64;

    const uint4* __restrict__ Wr128 = (const uint4*)g_Wrf;
    float rsum[2*MTN], rq[2*MTN];
    #pragma unroll
    for (int s = 0; s < 2*MTN; ++s) { rsum[s] = 0.0f; rq[s] = 0.0f; }

    // preload ch=0 ksl=0
    uint4 f0, f1;
    {
        const uint4* Bq = Wr128 + ((size_t)(warpid*32))*64 + lq;
        f0 = Bq[0]; f1 = Bq[1];
    }

    #pragma unroll
    for (int ch = 0; ch < 2; ++ch) {
        float acc[MTN][4][4];
        #pragma unroll
        for (int mt = 0; mt < MTN; ++mt)
            #pragma unroll
            for (int nt = 0; nt < 4; ++nt)
                #pragma unroll
                for (int c = 0; c < 4; ++c) acc[mt][nt][c] = 0.0f;

        const uint4* Bp = Wr128 + ((size_t)((ch*16 + warpid)*32))*64 + lq;

        for (int ksl = 0; ksl < 32; ++ksl) {
            uint4 n0, n1;
            if (ksl < 31) {
                const uint4* Bn = Bp + (size_t)(ksl + 1) * 64;
                n0 = Bn[0]; n1 = Bn[1];
            }
            uint32_t a[MTN][4];
            const uint32_t aaddr = h1b + ksl*32;
            #pragma unroll
            for (int mt = 0; mt < MTN; ++mt)
                LDSM4(a[mt], aaddr + mt*(16*HRW*4));
            #pragma unroll
            for (int mt = 0; mt < MTN; ++mt) {
                MMA_BF16(acc[mt][0], a[mt], f0.x, f0.y);
                MMA_BF16(acc[mt][1], a[mt], f0.z, f0.w);
                MMA_BF16(acc[mt][2], a[mt], f1.x, f1.y);
                MMA_BF16(acc[mt][3], a[mt], f1.z, f1.w);
            }
            f0 = n0; f1 = n1;
        }

        if (ch == 0) {  // prefetch ch=1 ksl=0 during epilogue
            const uint4* Bq = Wr128 + ((size_t)((16 + warpid)*32))*64 + lq;
            f0 = Bq[0]; f1 = Bq[1];
        }

        // epilogue: blend + residual, write pre-LN x, accumulate row stats
        #pragma unroll
        for (int mt = 0; mt < MTN; ++mt) {
            #pragma unroll
            for (int half = 0; half < 2; ++half) {
                const int row = mt*16 + g8 + half*8;
                const int R   = m0 + row;
                const float al = alf[R >> 9], ali = 1.0f - al;
                const float2 hv = *(const float2*)(habs + (size_t)R*2);
                const int slot = mt*2 + half;
                #pragma unroll
                for (int nt = 0; nt < 4; ++nt) {
                    const int col = ch*512 + warpid*32 + nt*8 + q*2;
                    float2 tk  = *(const float2*)(tokens + (size_t)R*DIM + col);
                    float2 wa0 = ((const float2*)W_abs)[col];
                    float2 wa1 = ((const float2*)W_abs)[col+1];
                    float x0 = tk.x + al*acc[mt][nt][half*2  ] + ali*(hv.x*wa0.x + hv.y*wa0.y);
                    float x1 = tk.y + al*acc[mt][nt][half*2+1] + ali*(hv.x*wa1.x + hv.y*wa1.y);
                    *(float2*)(out + (size_t)R*DIM + col) = make_float2(x0, x1);
                    rsum[slot] += x0 + x1;
                    rq[slot]   += x0*x0 + x1*x1;
                }
            }
        }
    }

    __syncthreads();
    #pragma unroll
    for (int mt = 0; mt < MTN; ++mt)
        #pragma unroll
        for (int half = 0; half < 2; ++half) {
            const int row = mt*16 + g8 + half*8;
            redS[row*64 + warpid*4 + q] = rsum[mt*2 + half];
            redQ[row*64 + warpid*4 + q] = rq[mt*2 + half];
        }
    __syncthreads();
    if (tid < ROWS) {
        float s = 0.0f, qq = 0.0f;
        #pragma unroll
        for (int i = 0; i < 64; ++i) { s += redS[tid*64 + i]; qq += redQ[tid*64 + i]; }
        float mu = s * (1.0f/DIM);
        float var = qq * (1.0f/DIM) - mu*mu;
        mu_s[tid] = mu; rs_s[tid] = rsqrtf(var + 1e-5f);
    }
    __syncthreads();

    for (int i = tid; i < ROWS*256; i += LTPB) {
        int mm = i >> 8, j4 = i & 255;
        float4 v = ((float4*)(out + (size_t)(m0 + mm)*DIM))[j4];
        float4 g = ((const float4*)gamma)[j4];
        float4 b = ((const float4*)beta)[j4];
        float mu = mu_s[mm], rr = rs_s[mm];
        v.x = (v.x - mu)*rr*g.x + b.x;
        v.y = (v.y - mu)*rr*g.y + b.y;
        v.z = (v.z - mu)*rr*g.z + b.z;
        v.w = (v.w - mu)*rr*g.w + b.w;
        ((float4*)(out + (size_t)(m0 + mm)*DIM))[j4] = v;
    }
}

// Mixed-size grid: CTAs 0..147 handle 64 rows, 148..291 handle 48 rows.
__global__ __launch_bounds__(LTPB, 1)
void lstm_fuse_kernel(const float* __restrict__ traj, const float* __restrict__ tokens,
                      const float* __restrict__ habs,
                      const float* __restrict__ espeed, const float* __restrict__ gconf,
                      const float* __restrict__ Wg1, const float* __restrict__ bg1,
                      const float* __restrict__ Wg2, const float* __restrict__ bg2,
                      const float* __restrict__ W_abs,
                      const float* __restrict__ gamma, const float* __restrict__ beta,
                      float* __restrict__ out)
{
    const int bid = blockIdx.x;
    if (bid < NCTA1)
        lstm_fuse_body<4>(traj, tokens, habs, espeed, gconf, Wg1, bg1, Wg2, bg2,
                          W_abs, gamma, beta, out, bid * 64);
    else
        lstm_fuse_body<3>(traj, tokens, habs, espeed, gconf, Wg1, bg1, Wg2, bg2,
                          W_abs, gamma, beta, out, NCTA1*64 + (bid - NCTA1) * 48);
}

// ---------------------------------------------------------------------------
extern "C" void kernel_launch(void* const* d_in, const int* in_sizes, int n_in,
                              void* d_out, int out_size)
{
    const float* tokens = (const float*)d_in[0];
    const float* traj   = (const float*)d_in[1];
    const float* habs   = (const float*)d_in[2];
    const float* espeed = (const float*)d_in[3];
    const float* gconf  = (const float*)d_in[4];
    const float* W_ih   = (const float*)d_in[5];
    const float* W_hh   = (const float*)d_in[6];
    const float* b_ih   = (const float*)d_in[7];
    const float* b_hh   = (const float*)d_in[8];
    const float* W_rel  = (const float*)d_in[9];
    const float* W_abs  = (const float*)d_in[10];
    const float* W_g1   = (const float*)d_in[11];
    const float* b_g1   = (const float*)d_in[12];
    const float* W_g2   = (const float*)d_in[13];
    const float* b_g2   = (const float*)d_in[14];
    const float* gamma  = (const float*)d_in[15];
    const float* beta   = (const float*)d_in[16];
    float* out = (float*)d_out;

    cudaFuncSetAttribute(lstm_fuse_kernel, cudaFuncAttributeMaxDynamicSharedMemorySize, LSMEM);

    reorder_kernel<<<G4 + DIM, 128>>>(W_hh, W_ih, b_ih, b_hh, W_rel);
    lstm_fuse_kernel<<<NCTA1 + NCTA2, LTPB, LSMEM>>>(
        traj, tokens, habs, espeed, gconf, W_g1, b_g1, W_g2, b_g2,
        W_abs, gamma, beta, out);
}

// round 16
// speedup vs baseline: 1.0264x; 1.0264x over previous
#include <cuda_runtime.h>
#include <cuda_bf16.h>
#include <cuda_fp16.h>
#include <math.h>
#include <stdint.h>
#include <string.h>

// ---------------- problem constants ----------------
#define BN      16384
#define HIDN    512
#define G4      2048
#define HLEN    15
#define DIM     1024

// ---------------- LSTM mma fp16 config ----------------
#define LTPB    512            // 16 warps (4 per SMSP)
#define NCTA1   148            // wave-1 CTAs: 64 rows
#define NCTA2   144            // wave-2 CTAs: 48 rows   (148*64+144*48 = 16384)
#define KSLN    33             // K slices: 512 h + 16 (x,1,pad)
#define HRW     268            // h row stride in u32 words (=536 halfs); conflict-free

// smem layout (bytes) — sized for 64 rows
#define OFF_H0   0              // 64*536*2 = 68608
#define OFF_H1   68608
#define OFF_C    137216         // c fp16 [32 half2 slots][512 tid]; reused as LN scratch in tail
#define OFF_TRJ  202752         // 64*60*4 = 15360
#define OFF_ALF  218112         // 32 f32 alphas
#define LSMEM    218240

// ---------------- device scratch ----------------
// W_hh(+W_ih+bias): per (pass,ksl,w16) tile of 256 u32 (f16x2): lane*8 + nt*2 + jj
__device__ uint32_t g_Wf [4*KSLN*16*256];
// W_rel: per (ch,w16,ksl) tile of 256 u32 (f16x2): lane*8 + nt*2 + jj
__device__ uint32_t g_Wrf[2*16*32*256];

// ---------------- helpers ----------------
__device__ __forceinline__ __half2 tanh2_ap(__half2 x){
    __half2 y;
    asm("tanh.approx.f16x2 %0, %1;" : "=r"(*(uint32_t*)&y) : "r"(*(const uint32_t*)&x));
    return y;
}
__device__ __forceinline__ __half2 sig2_ap(__half2 x){
    const __half2 hhalf = __floats2half2_rn(0.5f, 0.5f);
    return __hfma2(tanh2_ap(__hmul2(x, hhalf)), hhalf, hhalf);
}
__device__ __forceinline__ uint32_t smem_u32(const void* p){
    uint32_t a; asm("{ .reg .u64 t; cvta.to.shared.u64 t, %1; cvt.u32.u64 %0, t; }":"=r"(a):"l"(p)); return a;
}
#define MMA_F16(c, a, b0, b1) \
    asm volatile("mma.sync.aligned.m16n8k16.row.col.f32.f16.f16.f32 " \
        "{%0,%1,%2,%3}, {%4,%5,%6,%7}, {%8,%9}, {%0,%1,%2,%3};" \
        : "+f"((c)[0]), "+f"((c)[1]), "+f"((c)[2]), "+f"((c)[3]) \
        : "r"((a)[0]), "r"((a)[1]), "r"((a)[2]), "r"((a)[3]), "r"(b0), "r"(b1))
#define LDSM4(r, addr) \
    asm volatile("ldmatrix.sync.aligned.m8n8.x4.shared.b16 {%0,%1,%2,%3}, [%4];" \
        : "=r"((r)[0]), "=r"((r)[1]), "=r"((r)[2]), "=r"((r)[3]) : "r"(addr))

__device__ __forceinline__ uint32_t hf2(float a, float b){
    __half2 p = __floats2half2_rn(a, b);
    uint32_t u; memcpy(&u, &p, 4); return u;
}

// ---------------------------------------------------------------------------
// reorder: W_hh (+W_ih+bias slice 32) -> g_Wf (f16x2); W_rel -> g_Wrf (f16x2).
// ---------------------------------------------------------------------------
__global__ void reorder_kernel(const float* __restrict__ Whh, const float* __restrict__ Wih,
                               const float* __restrict__ bih, const float* __restrict__ bhh,
                               const float* __restrict__ Wrel)
{
    if (blockIdx.x < G4) {
        int n = blockIdx.x;
        int pass = n >> 9, w16 = (n >> 5) & 15, cw = n & 31;
        int j = cw >> 3, qq = (cw >> 1) & 3, r = cw & 1;
        int gate, ul;
        if (j < 2) { ul = j*4 + qq;     gate = r;     }
        else       { ul = (j-2)*4 + qq; gate = 2 + r; }
        int unit = pass*128 + w16*8 + ul;
        int srow = gate * HIDN + unit;

        const float* src = Whh + (size_t)srow * HIDN;
        float bsum = bih[srow] + bhh[srow];
        int colin = cw & 7;

        for (int k2 = threadIdx.x; k2 < (KSLN*16)/2; k2 += blockDim.x) {
            int k = k2 * 2;
            int ksl = k >> 4, kin = k & 15;
            float v0, v1;
            if (ksl < 32) { v0 = src[k]; v1 = src[k+1]; }
            else {
                v0 = (kin < 4) ? Wih[srow*4 + kin] : (kin == 4 ? bsum : 0.0f);
                v1 = (kin + 1 < 4) ? Wih[srow*4 + kin + 1] : 0.0f;
            }
            int jj = kin >> 3, qk = (kin >> 1) & 3;
            int lane = colin*4 + qk;
            size_t idx = ((size_t)((pass*KSLN + ksl)*16 + w16))*256 + lane*8 + j*2 + jj;
            g_Wf[idx] = hf2(v0, v1);
        }
    } else {
        int n = blockIdx.x - G4;            // output col 0..1023
        const float* src = Wrel + (size_t)n * HIDN;
        int ch = n >> 9, w16 = (n >> 5) & 15, nt = (n >> 3) & 3, colin = n & 7;
        for (int k2 = threadIdx.x; k2 < HIDN/2; k2 += blockDim.x) {
            int k = k2 * 2;
            int ksl = k >> 4, kin = k & 15;
            int jj = kin >> 3, qk = (kin >> 1) & 3;
            int lane = colin*4 + qk;
            size_t idx = ((size_t)((ch*16 + w16)*32 + ksl))*256 + lane*8 + nt*2 + jj;
            g_Wrf[idx] = hf2(src[k], src[k+1]);
        }
    }
}

// ---------------------------------------------------------------------------
// LSTM + fused projection/LN body, templated on m-tiles (4 -> 64 rows, 3 -> 48).
// fp16 inputs everywhere, fp32 accum; f16x2 paired activations.
// ---------------------------------------------------------------------------
template<int MTN>
__device__ __forceinline__ void lstm_fuse_body(
    const float* __restrict__ traj, const float* __restrict__ tokens,
    const float* __restrict__ habs,
    const float* __restrict__ espeed, const float* __restrict__ gconf,
    const float* __restrict__ Wg1, const float* __restrict__ bg1,
    const float* __restrict__ Wg2, const float* __restrict__ bg2,
    const float* __restrict__ W_abs,
    const float* __restrict__ gamma, const float* __restrict__ beta,
    float* __restrict__ out, int m0)
{
    extern __shared__ char smem[];
    float*   trj = (float*)  (smem + OFF_TRJ);
    __half2* c_s = (__half2*)(smem + OFF_C);     // [32 slots][512 tid]
    float*   alf = (float*)  (smem + OFF_ALF);
    const int ROWS = MTN * 16;

    const int tid = threadIdx.x;
    const int lane = tid & 31, warpid = tid >> 5;
    const int q = lane & 3, g8 = lane >> 2;

    // per-CTA alpha gate for all 32 batches (tiny MLP)
    if (tid < 32) {
        float s = espeed[tid], cg = gconf[tid];
        float acc = bg2[0];
        #pragma unroll
        for (int h = 0; h < 16; ++h) {
            float tv = Wg1[2*h]*s + Wg1[2*h+1]*cg + bg1[h];
            acc += Wg2[h] * fmaxf(tv, 0.0f);
        }
        alf[tid] = 1.0f / (1.0f + expf(-acc));
    }

    for (int i = tid; i < (ROWS*HLEN*4)/4; i += LTPB)
        ((float4*)trj)[i] = ((const float4*)(traj + (size_t)m0 * (HLEN*4)))[i];
    if (tid < ROWS) {
        float4 xv = *(const float4*)(traj + (size_t)(m0 + tid) * (HLEN*4));
        uint32_t* dst = (uint32_t*)(smem + OFF_H0) + tid*HRW + 256;
        dst[0] = hf2(xv.x, xv.y); dst[1] = hf2(xv.z, xv.w); dst[2] = hf2(1.0f, 0.0f);
        dst[3] = 0; dst[4] = 0; dst[5] = 0; dst[6] = 0; dst[7] = 0;
    }
    __syncthreads();

    const uint4* __restrict__ Wf128 = (const uint4*)g_Wf;
    const uint32_t lmoff = (((lane & 15) * HRW + ((lane >> 4) << 2)) << 2);
    const uint32_t h0b = smem_u32(smem + OFF_H0) + lmoff;
    const uint32_t h1b = smem_u32(smem + OFF_H1) + lmoff;
    const uint32_t lq = (uint32_t)lane * 2;      // uint4 offset within tile

    // persistent B stage: preload (t=0, ncp=0, ksl=KSLN-1)
    uint4 c0, c1;
    {
        const uint4* B0 = Wf128 + ((size_t)((0*KSLN + (KSLN-1))*16 + warpid))*64 + lq;
        c0 = B0[0]; c1 = B0[1];
    }

    for (int t = 0; t < HLEN; ++t) {
        const uint32_t hcur_b = (t & 1) ? h1b : h0b;
        char*   hnb  = smem + ((t & 1) ? OFF_H0 : OFF_H1);
        __half* hnxt = (__half*)hnb;

        for (int ncp = 0; ncp < 4; ++ncp) {
            float acc[MTN][4][4];
            #pragma unroll
            for (int mt = 0; mt < MTN; ++mt)
                #pragma unroll
                for (int nt = 0; nt < 4; ++nt)
                    #pragma unroll
                    for (int c = 0; c < 4; ++c) acc[mt][nt][c] = 0.0f;

            const int ks0 = (t == 0) ? (KSLN - 1) : 0;
            const uint4* Bp = Wf128 + ((size_t)(ncp*KSLN*16) + warpid)*64 + lq;

            for (int ksl = ks0; ksl < KSLN; ++ksl) {
                uint4 n0, n1;
                if (ksl < KSLN - 1) {
                    const uint4* Bn = Bp + (size_t)(ksl + 1) * 1024;
                    n0 = Bn[0]; n1 = Bn[1];
                }
                uint32_t a[MTN][4];
                const uint32_t aaddr = hcur_b + ksl*32;
                #pragma unroll
                for (int mt = 0; mt < MTN; ++mt)
                    LDSM4(a[mt], aaddr + mt*(16*HRW*4));
                #pragma unroll
                for (int mt = 0; mt < MTN; ++mt) {
                    MMA_F16(acc[mt][0], a[mt], c0.x, c0.y);
                    MMA_F16(acc[mt][1], a[mt], c0.z, c0.w);
                    MMA_F16(acc[mt][2], a[mt], c1.x, c1.y);
                    MMA_F16(acc[mt][3], a[mt], c1.z, c1.w);
                }
                c0 = n0; c1 = n1;
            }

            // prefetch next (pass, step)'s first B tile — overlaps epilogue
            {
                int tn = t, ncpn = ncp + 1;
                if (ncpn == 4) { ncpn = 0; tn = t + 1; }
                if (tn < HLEN) {
                    int ks0n = (tn == 0) ? (KSLN - 1) : 0;
                    const uint4* Bq = Wf128 + ((size_t)((ncpn*KSLN + ks0n)*16) + warpid)*64 + lq;
                    c0 = Bq[0]; c1 = Bq[1];
                }
            }

            // ---- epilogue: paired f16x2 activations (units j2=0,1 packed) ----
            const int kg0 = ncp*128 + warpid*8 + q;
            #pragma unroll
            for (int mt = 0; mt < MTN; ++mt) {
                #pragma unroll
                for (int half = 0; half < 2; ++half) {
                    const int row = mt*16 + g8 + half*8;
                    const int h2i = half*2;
                    __half2 gi2 = __floats2half2_rn(acc[mt][0][h2i  ], acc[mt][1][h2i  ]);
                    __half2 gf2 = __floats2half2_rn(acc[mt][0][h2i+1], acc[mt][1][h2i+1]);
                    __half2 gg2 = __floats2half2_rn(acc[mt][2][h2i  ], acc[mt][3][h2i  ]);
                    __half2 go2 = __floats2half2_rn(acc[mt][2][h2i+1], acc[mt][3][h2i+1]);
                    const int cidx = (ncp*8 + mt*2 + half)*LTPB + tid;
                    __half2 cp2 = (t > 0) ? c_s[cidx] : __floats2half2_rn(0.0f, 0.0f);
                    __half2 cn2 = __hfma2(sig2_ap(gf2), cp2,
                                          __hmul2(sig2_ap(gi2), tanh2_ap(gg2)));
                    c_s[cidx] = cn2;
                    __half2 hn2 = __hmul2(sig2_ap(go2), tanh2_ap(cn2));
                    hnxt[row*536 + kg0    ] = __low2half(hn2);
                    hnxt[row*536 + kg0 + 4] = __high2half(hn2);
                }
            }
        }

        if (t < HLEN - 1 && tid < ROWS) {
            float4 xv = *(const float4*)(trj + tid*60 + (t+1)*4);
            uint32_t* dst = (uint32_t*)hnb + tid*HRW + 256;
            dst[0] = hf2(xv.x, xv.y); dst[1] = hf2(xv.z, xv.w); dst[2] = hf2(1.0f, 0.0f);
            dst[3] = 0; dst[4] = 0; dst[5] = 0; dst[6] = 0; dst[7] = 0;
        }
        __syncthreads();
    }

    // =======================================================================
    // fuse tail: out = LN(tokens + al*(h15 @ W_rel^T) + (1-al)*(habs @ W_abs^T))
    // =======================================================================
    float* redS = (float*)(smem + OFF_C);      // [64][64]
    float* redQ = redS + 64*64;
    float* mu_s = redQ + 64*64;
    float* rs_s = mu_s + 64;

    const uint4* __restrict__ Wr128 = (const uint4*)g_Wrf;
    float rsum[2*MTN], rq[2*MTN];
    #pragma unroll
    for (int s = 0; s < 2*MTN; ++s) { rsum[s] = 0.0f; rq[s] = 0.0f; }

    // preload ch=0 ksl=0
    uint4 f0, f1;
    {
        const uint4* Bq = Wr128 + ((size_t)(warpid*32))*64 + lq;
        f0 = Bq[0]; f1 = Bq[1];
    }

    #pragma unroll
    for (int ch = 0; ch < 2; ++ch) {
        float acc[MTN][4][4];
        #pragma unroll
        for (int mt = 0; mt < MTN; ++mt)
            #pragma unroll
            for (int nt = 0; nt < 4; ++nt)
                #pragma unroll
                for (int c = 0; c < 4; ++c) acc[mt][nt][c] = 0.0f;

        const uint4* Bp = Wr128 + ((size_t)((ch*16 + warpid)*32))*64 + lq;

        for (int ksl = 0; ksl < 32; ++ksl) {
            uint4 n0, n1;
            if (ksl < 31) {
                const uint4* Bn = Bp + (size_t)(ksl + 1) * 64;
                n0 = Bn[0]; n1 = Bn[1];
            }
            uint32_t a[MTN][4];
            const uint32_t aaddr = h1b + ksl*32;
            #pragma unroll
            for (int mt = 0; mt < MTN; ++mt)
                LDSM4(a[mt], aaddr + mt*(16*HRW*4));
            #pragma unroll
            for (int mt = 0; mt < MTN; ++mt) {
                MMA_F16(acc[mt][0], a[mt], f0.x, f0.y);
                MMA_F16(acc[mt][1], a[mt], f0.z, f0.w);
                MMA_F16(acc[mt][2], a[mt], f1.x, f1.y);
                MMA_F16(acc[mt][3], a[mt], f1.z, f1.w);
            }
            f0 = n0; f1 = n1;
        }

        if (ch == 0) {  // prefetch ch=1 ksl=0 during epilogue
            const uint4* Bq = Wr128 + ((size_t)((16 + warpid)*32))*64 + lq;
            f0 = Bq[0]; f1 = Bq[1];
        }

        // epilogue: blend + residual, write pre-LN x, accumulate row stats
        #pragma unroll
        for (int mt = 0; mt < MTN; ++mt) {
            #pragma unroll
            for (int half = 0; half < 2; ++half) {
                const int row = mt*16 + g8 + half*8;
                const int R   = m0 + row;
                const float al = alf[R >> 9], ali = 1.0f - al;
                const float2 hv = *(const float2*)(habs + (size_t)R*2);
                const int slot = mt*2 + half;
                #pragma unroll
                for (int nt = 0; nt < 4; ++nt) {
                    const int col = ch*512 + warpid*32 + nt*8 + q*2;
                    float2 tk  = *(const float2*)(tokens + (size_t)R*DIM + col);
                    float2 wa0 = ((const float2*)W_abs)[col];
                    float2 wa1 = ((const float2*)W_abs)[col+1];
                    float x0 = tk.x + al*acc[mt][nt][half*2  ] + ali*(hv.x*wa0.x + hv.y*wa0.y);
                    float x1 = tk.y + al*acc[mt][nt][half*2+1] + ali*(hv.x*wa1.x + hv.y*wa1.y);
                    *(float2*)(out + (size_t)R*DIM + col) = make_float2(x0, x1);
                    rsum[slot] += x0 + x1;
                    rq[slot]   += x0*x0 + x1*x1;
                }
            }
        }
    }

    __syncthreads();
    #pragma unroll
    for (int mt = 0; mt < MTN; ++mt)
        #pragma unroll
        for (int half = 0; half < 2; ++half) {
            const int row = mt*16 + g8 + half*8;
            redS[row*64 + warpid*4 + q] = rsum[mt*2 + half];
            redQ[row*64 + warpid*4 + q] = rq[mt*2 + half];
        }
    __syncthreads();
    if (tid < ROWS) {
        float s = 0.0f, qq = 0.0f;
        #pragma unroll
        for (int i = 0; i < 64; ++i) { s += redS[tid*64 + i]; qq += redQ[tid*64 + i]; }
        float mu = s * (1.0f/DIM);
        float var = qq * (1.0f/DIM) - mu*mu;
        mu_s[tid] = mu; rs_s[tid] = rsqrtf(var + 1e-5f);
    }
    __syncthreads();

    for (int i = tid; i < ROWS*256; i += LTPB) {
        int mm = i >> 8, j4 = i & 255;
        float4 v = ((float4*)(out + (size_t)(m0 + mm)*DIM))[j4];
        float4 g = ((const float4*)gamma)[j4];
        float4 b = ((const float4*)beta)[j4];
        float mu = mu_s[mm], rr = rs_s[mm];
        v.x = (v.x - mu)*rr*g.x + b.x;
        v.y = (v.y - mu)*rr*g.y + b.y;
        v.z = (v.z - mu)*rr*g.z + b.z;
        v.w = (v.w - mu)*rr*g.w + b.w;
        ((float4*)(out + (size_t)(m0 + mm)*DIM))[j4] = v;
    }
}

// Mixed-size grid: CTAs 0..147 handle 64 rows, 148..291 handle 48 rows.
__global__ __launch_bounds__(LTPB, 1)
void lstm_fuse_kernel(const float* __restrict__ traj, const float* __restrict__ tokens,
                      const float* __restrict__ habs,
                      const float* __restrict__ espeed, const float* __restrict__ gconf,
                      const float* __restrict__ Wg1, const float* __restrict__ bg1,
                      const float* __restrict__ Wg2, const float* __restrict__ bg2,
                      const float* __restrict__ W_abs,
                      const float* __restrict__ gamma, const float* __restrict__ beta,
                      float* __restrict__ out)
{
    const int bid = blockIdx.x;
    if (bid < NCTA1)
        lstm_fuse_body<4>(traj, tokens, habs, espeed, gconf, Wg1, bg1, Wg2, bg2,
                          W_abs, gamma, beta, out, bid * 64);
    else
        lstm_fuse_body<3>(traj, tokens, habs, espeed, gconf, Wg1, bg1, Wg2, bg2,
                          W_abs, gamma, beta, out, NCTA1*64 + (bid - NCTA1) * 48);
}

// ---------------------------------------------------------------------------
extern "C" void kernel_launch(void* const* d_in, const int* in_sizes, int n_in,
                              void* d_out, int out_size)
{
    const float* tokens = (const float*)d_in[0];
    const float* traj   = (const float*)d_in[1];
    const float* habs   = (const float*)d_in[2];
    const float* espeed = (const float*)d_in[3];
    const float* gconf  = (const float*)d_in[4];
    const float* W_ih   = (const float*)d_in[5];
    const float* W_hh   = (const float*)d_in[6];
    const float* b_ih   = (const float*)d_in[7];
    const float* b_hh   = (const float*)d_in[8];
    const float* W_rel  = (const float*)d_in[9];
    const float* W_abs  = (const float*)d_in[10];
    const float* W_g1   = (const float*)d_in[11];
    const float* b_g1   = (const float*)d_in[12];
    const float* W_g2   = (const float*)d_in[13];
    const float* b_g2   = (const float*)d_in[14];
    const float* gamma  = (const float*)d_in[15];
    const float* beta   = (const float*)d_in[16];
    float* out = (float*)d_out;

    cudaFuncSetAttribute(lstm_fuse_kernel, cudaFuncAttributeMaxDynamicSharedMemorySize, LSMEM);

    reorder_kernel<<<G4 + DIM, 128>>>(W_hh, W_ih, b_ih, b_hh, W_rel);
    lstm_fuse_kernel<<<NCTA1 + NCTA2, LTPB, LSMEM>>>(
        traj, tokens, habs, espeed, gconf, W_g1, b_g1, W_g2, b_g2,
        W_abs, gamma, beta, out);
}